// round 15
// baseline (speedup 1.0000x reference)
#include <cuda_runtime.h>
#include <cuda_fp16.h>

#define IN_DIM 128
#define HEADS 8
#define ODIM 32
#define HID 256            // HEADS*ODIM
#define NEG 0.2f
#define NMAX 50000
#define EMAX 800000
#define WELEM (IN_DIM * HID)   // 32768

// GEMM tiling: block 64x256, k-tile 32, warps 4(M) x 2(N), warp tile 16x128
#define BM 64
#define XS_STRIDE 36
#define WS_STRIDE 264
#define XS_FLOATS (64 * XS_STRIDE)                 // 2304
#define WS_FLOATS (32 * WS_STRIDE)                 // 8448
#define BUF_FLOATS (XS_FLOATS + WS_FLOATS)         // 10752
#define SMEM_FLOATS (2 * BUF_FLOATS)               // 84 KB -> 2 CTAs/SM
#define D_STRIDE 260

// ---------------- device scratch (static: no allocation allowed) -------------
__device__ __half g_hh[NMAX * HID];      // 25.6 MB (fp16 messages)
__device__ float  g_asrc[NMAX * HEADS];
__device__ float  g_adst[NMAX * HEADS];
__device__ float  g_wt[WELEM];           // W pre-rounded to tf32 bit pattern
__device__ int    g_deg[NMAX];
__device__ int    g_rank[EMAX];          // edge rank within its dst bucket
__device__ int    g_off[NMAX + 1];
__device__ int    g_csrc[EMAX];
__device__ int    g_bsum[256];
__device__ int    g_bbase[256];

// ---------------- helpers ----------------------------------------------------
__device__ __forceinline__ void cp16(void* dst, const void* src, bool pred) {
    unsigned d = (unsigned)__cvta_generic_to_shared(dst);
    int sz = pred ? 16 : 0;
    asm volatile("cp.async.cg.shared.global [%0], [%1], 16, %2;"
                 :: "r"(d), "l"(src), "r"(sz) : "memory");
}
__device__ __forceinline__ unsigned tf32u(float v) {
    unsigned u;
    asm("cvt.rna.tf32.f32 %0, %1;" : "=r"(u) : "f"(v));
    return u;
}
__device__ __forceinline__ void mma_tf32(float4& d,
    unsigned a0, unsigned a1, unsigned a2, unsigned a3,
    unsigned b0, unsigned b1)
{
    asm volatile(
        "mma.sync.aligned.m16n8k8.row.col.f32.tf32.tf32.f32 "
        "{%0,%1,%2,%3}, {%4,%5,%6,%7}, {%8,%9}, {%0,%1,%2,%3};"
        : "+f"(d.x), "+f"(d.y), "+f"(d.z), "+f"(d.w)
        : "r"(a0), "r"(a1), "r"(a2), "r"(a3), "r"(b0), "r"(b1));
}

// ---------------- zero + W->tf32 pre-convert ---------------------------------
__global__ void zero_kernel(const float* __restrict__ W, int n) {
    int i = blockIdx.x * blockDim.x + threadIdx.x;
    if (i < n) g_deg[i] = 0;
    if (i < WELEM) g_wt[i] = __uint_as_float(tf32u(W[i]));
}

// ---------------- tf32 tensor-core GEMM + fused attention dots ---------------
__global__ void __launch_bounds__(256, 2) gemm_kernel(
    const float* __restrict__ x,
    const float* __restrict__ att_s, const float* __restrict__ att_d, int n)
{
    extern __shared__ float smem[];
    float* xsb[2] = { smem,             smem + BUF_FLOATS };
    float* wsb[2] = { smem + XS_FLOATS, smem + BUF_FLOATS + XS_FLOATS };

    int tid  = threadIdx.x;
    int lane = tid & 31, wid = tid >> 5;
    int g    = lane >> 2, tig = lane & 3;
    int wm   = wid & 3,   wn  = wid >> 2;      // 4(M) x 2(N)
    int row0 = blockIdx.x * BM;

    auto issue = [&](int kt, int b) {
        float* xs = xsb[b];
        float* ws = wsb[b];
        #pragma unroll
        for (int t = 0; t < 2; t++) {
            int q = tid + t * 256;
            int r = q >> 3, k4 = q & 7;
            int grow = row0 + r;
            cp16(xs + r * XS_STRIDE + k4 * 4,
                 x + (size_t)grow * IN_DIM + kt * 32 + k4 * 4, grow < n);
        }
        #pragma unroll
        for (int t = 0; t < 8; t++) {
            int q = tid + t * 256;
            int r = q >> 6, c4 = q & 63;
            cp16(ws + r * WS_STRIDE + c4 * 4,
                 g_wt + (size_t)(kt * 32 + r) * 256 + c4 * 4, true);
        }
        asm volatile("cp.async.commit_group;" ::: "memory");
    };

    float4 acc[16];
    #pragma unroll
    for (int t = 0; t < 16; t++) acc[t] = make_float4(0.f, 0.f, 0.f, 0.f);

    issue(0, 0);

    #pragma unroll
    for (int kt = 0; kt < 4; kt++) {
        if (kt < 3) issue(kt + 1, (kt + 1) & 1);
        if (kt < 3) asm volatile("cp.async.wait_group 1;" ::: "memory");
        else        asm volatile("cp.async.wait_group 0;" ::: "memory");
        __syncthreads();

        const float* xs = xsb[kt & 1];
        const float* ws = wsb[kt & 1];
        #pragma unroll
        for (int ks = 0; ks < 4; ks++) {
            int kk = ks * 8;
            const float* xa = xs + (wm * 16) * XS_STRIDE + kk;
            unsigned a0 = tf32u(xa[g * XS_STRIDE + tig]);
            unsigned a1 = tf32u(xa[(g + 8) * XS_STRIDE + tig]);
            unsigned a2 = tf32u(xa[g * XS_STRIDE + tig + 4]);
            unsigned a3 = tf32u(xa[(g + 8) * XS_STRIDE + tig + 4]);
            const float* wb = ws + kk * WS_STRIDE + wn * 128 + g;
            #pragma unroll
            for (int nc = 0; nc < 4; nc++) {
                unsigned bq[8];
                #pragma unroll
                for (int j = 0; j < 4; j++) {
                    int nt = nc * 4 + j;
                    bq[2 * j]     = __float_as_uint(wb[tig * WS_STRIDE + nt * 8]);
                    bq[2 * j + 1] = __float_as_uint(wb[(tig + 4) * WS_STRIDE + nt * 8]);
                }
                #pragma unroll
                for (int j = 0; j < 4; j++)
                    mma_tf32(acc[nc * 4 + j], a0, a1, a2, a3, bq[2 * j], bq[2 * j + 1]);
            }
        }
        __syncthreads();
    }

    // ---- epilogue: D -> smem row-major, then h + dots -----------------------
    float* Dsm = smem;
    {
        int rbase = wm * 16;
        int cbase = wn * 128 + tig * 2;
        #pragma unroll
        for (int nt = 0; nt < 16; nt++) {
            int c = cbase + nt * 8;
            *(float2*)(Dsm + (rbase + g) * D_STRIDE + c)     = make_float2(acc[nt].x, acc[nt].y);
            *(float2*)(Dsm + (rbase + g + 8) * D_STRIDE + c) = make_float2(acc[nt].z, acc[nt].w);
        }
    }
    __syncthreads();

    {
        int row  = tid >> 2, part = tid & 3;
        int grow = row0 + row;
        if (grow < n) {
            int c0 = part * 64;
            float d[64];
            #pragma unroll
            for (int i = 0; i < 16; i++)
                *(float4*)(d + i * 4) = *(const float4*)(Dsm + row * D_STRIDE + c0 + i * 4);

            __half2 hv[4];
            #pragma unroll
            for (int i = 0; i < 8; i++) {
                #pragma unroll
                for (int p = 0; p < 4; p++)
                    hv[p] = __floats2half2_rn(d[i * 8 + 2 * p], d[i * 8 + 2 * p + 1]);
                *(uint4*)(g_hh + (size_t)grow * HID + c0 + i * 8) = *(uint4*)hv;
            }

            float s0 = 0.f, s1 = 0.f, t0 = 0.f, t1 = 0.f;
            #pragma unroll
            for (int j = 0; j < 32; j++) {
                s0 += d[j]      * att_s[c0 + j];
                t0 += d[j]      * att_d[c0 + j];
                s1 += d[j + 32] * att_s[c0 + 32 + j];
                t1 += d[j + 32] * att_d[c0 + 32 + j];
            }
            int h0 = 2 * part;
            g_asrc[grow * HEADS + h0]     = s0;
            g_asrc[grow * HEADS + h0 + 1] = s1;
            g_adst[grow * HEADS + h0]     = t0;
            g_adst[grow * HEADS + h0 + 1] = t1;
        }
    }
}

// ---------------- degree histogram + per-edge rank ---------------------------
__global__ void deg_kernel(const int* __restrict__ ei, int e, int n) {
    int i = blockIdx.x * blockDim.x + threadIdx.x;
    if (i < e) {
        int d = ei[e + i];   // dst row of edge_index [2, E]
        int r = 0;
        if ((unsigned)d < (unsigned)n) r = atomicAdd(&g_deg[d], 1);
        g_rank[i] = r;
    }
}

// ---------------- 3-kernel exclusive scan ------------------------------------
__device__ __forceinline__ int block_scan_incl(int v, int tid) {
    __shared__ int wsum[8];
    int lane = tid & 31, w = tid >> 5;
    int x = v;
    #pragma unroll
    for (int o = 1; o < 32; o <<= 1) {
        int y = __shfl_up_sync(0xffffffffu, x, o);
        if (lane >= o) x += y;
    }
    if (lane == 31) wsum[w] = x;
    __syncthreads();
    if (tid < 8) {
        int y = wsum[tid];
        #pragma unroll
        for (int o = 1; o < 8; o <<= 1) {
            int z = __shfl_up_sync(0xffu, y, o);
            if (tid >= o) y += z;
        }
        wsum[tid] = y;
    }
    __syncthreads();
    int base = (w > 0) ? wsum[w - 1] : 0;
    return x + base;
}

__global__ void scan_a_kernel(int n) {
    int i = blockIdx.x * 256 + threadIdx.x;
    int v = (i < n) ? g_deg[i] : 0;
    int incl = block_scan_incl(v, threadIdx.x);
    if (i < n) g_off[i] = incl - v;
    if (threadIdx.x == 255) g_bsum[blockIdx.x] = incl;
}

__global__ void scan_b_kernel(int nb) {
    int t = threadIdx.x;
    int v = (t < nb) ? g_bsum[t] : 0;
    int incl = block_scan_incl(v, t);
    g_bbase[t] = incl - v;
}

__global__ void scan_c_kernel(int n, int e) {
    int i = blockIdx.x * 256 + threadIdx.x;
    if (i < n) g_off[i] += g_bbase[blockIdx.x];
    if (i == 0) g_off[n] = e;
}

// ---------------- CSR fill (atomic-free: uses deg-phase ranks) ---------------
__global__ void fill_kernel(const int* __restrict__ ei, int e, int n) {
    int i = blockIdx.x * blockDim.x + threadIdx.x;
    if (i < e) {
        int d = ei[e + i];
        int s = ei[i];
        if ((unsigned)d < (unsigned)n)
            g_csrc[g_off[d] + g_rank[i]] = s;
    }
}

// ---------------- single-pass softmax + aggregate (4-edge groups, pipelined) -
// Logit layout: lane = (edge-slot lane>>3, head lane&7). Next group's src +
// a_src are prefetched before the current group's h-load/FMA phase, so the
// 234-cyc logit latency overlaps compute. Tail groups skip invalid h-loads
// via the warp-uniform jmax predicate (kills ~8% padded traffic).
__global__ __launch_bounds__(256) void agg_kernel(
    const float* __restrict__ bias, float* __restrict__ out, int n)
{
    int warp = (blockIdx.x * blockDim.x + threadIdx.x) >> 5;
    int lane = threadIdx.x & 31;
    if (warp >= n) return;
    int node = warp;
    int beg = g_off[node];
    int cnt = g_off[node + 1] - beg + 1;     // edges + self loop

    int eslot = lane >> 3, head8 = lane & 7; // logit role
    int hsel  = lane >> 2;                   // accumulation head

    float adl = g_adst[node * HEADS + head8];

    float acc[8];
    #pragma unroll
    for (int j = 0; j < 8; j++) acc[j] = 0.f;
    float s_part = 0.f;                      // partial denom for head8

    // prologue: group 0 logits
    int pos0 = eslot;
    int src_e = (pos0 < cnt - 1) ? g_csrc[beg + pos0] : node;
    float a = g_asrc[src_e * HEADS + head8];

    for (int base = 0; base < cnt; base += 4) {
        bool valid = (base + eslot) < cnt;
        float ev = a + adl;
        ev = ev > 0.f ? ev : NEG * ev;
        float ex = valid ? __expf(ev) : 0.f;
        s_part += ex;
        int src_cur = src_e;

        // prefetch next group's logits (overlaps the h phase below)
        if (base + 4 < cnt) {
            int p = base + 4 + eslot;
            src_e = (p < cnt - 1) ? g_csrc[beg + p] : node;
            a = g_asrc[src_e * HEADS + head8];
        }

        int jmax = cnt - base; jmax = jmax > 4 ? 4 : jmax;   // warp-uniform
        int   sj[4];
        float exj[4];
        #pragma unroll
        for (int j = 0; j < 4; j++) {
            sj[j]  = __shfl_sync(0xffffffffu, src_cur, j * 8);
            exj[j] = __shfl_sync(0xffffffffu, ex, j * 8 + hsel);
        }
        uint4 hr[4];
        #pragma unroll
        for (int j = 0; j < 4; j++)
            if (j < jmax)
                hr[j] = *(const uint4*)(g_hh + (size_t)sj[j] * HID + lane * 8);
        #pragma unroll
        for (int j = 0; j < 4; j++)
            if (j < jmax) {
                const __half2* hh = (const __half2*)&hr[j];
                #pragma unroll
                for (int k2 = 0; k2 < 4; k2++) {
                    float2 f = __half22float2(hh[k2]);
                    acc[2 * k2]     = fmaf(exj[j], f.x, acc[2 * k2]);
                    acc[2 * k2 + 1] = fmaf(exj[j], f.y, acc[2 * k2 + 1]);
                }
            }
    }

    // fold the 4 edge-slot groups' denominators (lanes with same head8)
    s_part += __shfl_xor_sync(0xffffffffu, s_part, 8);
    s_part += __shfl_xor_sync(0xffffffffu, s_part, 16);
    float inv_l = __frcp_rn(s_part);         // every lane: inv for head8
    float invk = __shfl_sync(0xffffffffu, inv_l, hsel) * 0.125f;
    #pragma unroll
    for (int j = 0; j < 8; j++) acc[j] *= invk;
    #pragma unroll
    for (int o = 4; o < 32; o <<= 1)
        #pragma unroll
        for (int j = 0; j < 8; j++)
            acc[j] += __shfl_xor_sync(0xffffffffu, acc[j], o);

    if (lane < 4) {
        int c0 = lane * 8;
        float4 o0 = make_float4(acc[0] + bias[c0],     acc[1] + bias[c0 + 1],
                                acc[2] + bias[c0 + 2], acc[3] + bias[c0 + 3]);
        float4 o1 = make_float4(acc[4] + bias[c0 + 4], acc[5] + bias[c0 + 5],
                                acc[6] + bias[c0 + 6], acc[7] + bias[c0 + 7]);
        *(float4*)(out + node * ODIM + c0)     = o0;
        *(float4*)(out + node * ODIM + c0 + 4) = o1;
    }
}

// ---------------- launcher: fork/join stream overlap -------------------------
extern "C" void kernel_launch(void* const* d_in, const int* in_sizes, int n_in,
                              void* d_out, int out_size)
{
    const float* x     = (const float*)d_in[0];
    const int*   ei    = (const int*)d_in[1];   // [2, E] — int32 (JAX x64 off)
    const float* W     = (const float*)d_in[3];
    const float* att_s = (const float*)d_in[4];
    const float* att_d = (const float*)d_in[5];
    const float* bias  = (const float*)d_in[6];
    float*       out   = (float*)d_out;

    int n = in_sizes[0] / IN_DIM;
    int e = in_sizes[1] / 2;
    int nb = (n + 255) / 256;
    const int smem_bytes = SMEM_FLOATS * 4;   // 86016 B

    cudaFuncSetAttribute(gemm_kernel,
                         cudaFuncAttributeMaxDynamicSharedMemorySize, smem_bytes);

    cudaStream_t s1;
    cudaEvent_t ev_fork, ev_join;
    cudaStreamCreateWithFlags(&s1, cudaStreamNonBlocking);
    cudaEventCreateWithFlags(&ev_fork, cudaEventDisableTiming);
    cudaEventCreateWithFlags(&ev_join, cudaEventDisableTiming);

    // main stream: zero (g_deg + W cvt) first — both branches depend on it
    zero_kernel<<<nb, 256, 0, 0>>>(W, n);
    cudaEventRecord(ev_fork, 0);

    // side stream: CSR build chain
    cudaStreamWaitEvent(s1, ev_fork, 0);
    deg_kernel<<<(e + 255) / 256, 256, 0, s1>>>(ei, e, n);
    scan_a_kernel<<<nb, 256, 0, s1>>>(n);
    scan_b_kernel<<<1, 256, 0, s1>>>(nb);
    scan_c_kernel<<<nb, 256, 0, s1>>>(n, e);
    fill_kernel<<<(e + 255) / 256, 256, 0, s1>>>(ei, e, n);
    cudaEventRecord(ev_join, s1);

    // main stream: GEMM concurrently with CSR build
    gemm_kernel<<<(n + BM - 1) / BM, 256, smem_bytes, 0>>>(x, att_s, att_d, n);

    // join, then aggregate
    cudaStreamWaitEvent(0, ev_join, 0);
    agg_kernel<<<(n * 32 + 255) / 256, 256, 0, 0>>>(bias, out, n);
}

// round 16
// speedup vs baseline: 1.0343x; 1.0343x over previous
#include <cuda_runtime.h>
#include <cuda_fp16.h>

#define IN_DIM 128
#define HEADS 8
#define ODIM 32
#define HID 256            // HEADS*ODIM
#define NEG 0.2f
#define NMAX 50000
#define EMAX 800000
#define WELEM (IN_DIM * HID)   // 32768

// fp16 GEMM: block 64x256, single K=128 tile, warps 4(M) x 2(N), m16n8k16
#define BM 64
#define XS16_STRIDE 136        // fp16 units; 68 words -> 4g+tig banks, conflict-free
#define WS16_STRIDE 136
#define XS16_BYTES (64 * XS16_STRIDE * 2)     // 17408
#define WS16_BYTES (256 * WS16_STRIDE * 2)    // 69632
#define GSMEM_BYTES (XS16_BYTES + WS16_BYTES) // 87040 -> 2 CTAs/SM (174KB)
#define D_STRIDE 260

// ---------------- device scratch (static: no allocation allowed) -------------
__device__ __half g_hh[NMAX * HID];        // 25.6 MB (fp16 messages)
__device__ __half g_x16[NMAX * IN_DIM];    // 12.8 MB (fp16 x)
__device__ __half g_wt16[WELEM];           // W transposed [n][k], fp16
__device__ float  g_asrc[NMAX * HEADS];
__device__ float  g_adst[NMAX * HEADS];
__device__ int    g_deg[NMAX];
__device__ int    g_rank[EMAX];            // edge rank within its dst bucket
__device__ int    g_off[NMAX + 1];
__device__ int    g_csrc[EMAX];
__device__ int    g_bsum[256];
__device__ int    g_bbase[256];

// ---------------- helpers ----------------------------------------------------
__device__ __forceinline__ void cp16(void* dst, const void* src, bool pred) {
    unsigned d = (unsigned)__cvta_generic_to_shared(dst);
    int sz = pred ? 16 : 0;
    asm volatile("cp.async.cg.shared.global [%0], [%1], 16, %2;"
                 :: "r"(d), "l"(src), "r"(sz) : "memory");
}
__device__ __forceinline__ void mma_f16(float4& d,
    unsigned a0, unsigned a1, unsigned a2, unsigned a3,
    unsigned b0, unsigned b1)
{
    asm volatile(
        "mma.sync.aligned.m16n8k16.row.col.f32.f16.f16.f32 "
        "{%0,%1,%2,%3}, {%4,%5,%6,%7}, {%8,%9}, {%0,%1,%2,%3};"
        : "+f"(d.x), "+f"(d.y), "+f"(d.z), "+f"(d.w)
        : "r"(a0), "r"(a1), "r"(a2), "r"(a3), "r"(b0), "r"(b1));
}

// ---------------- zero + W->fp16 transpose pre-convert -----------------------
__global__ void zero_kernel(const float* __restrict__ W, int n) {
    int i = blockIdx.x * blockDim.x + threadIdx.x;
    if (i < n) g_deg[i] = 0;
    if (i < WELEM) {
        int k = i >> 8, nn = i & 255;          // W row-major [k][256]
        g_wt16[nn * IN_DIM + k] = __float2half_rn(W[i]);
    }
}

// ---------------- x -> fp16 convert ------------------------------------------
__global__ void xcvt_kernel(const float* __restrict__ x, int total4) {
    int i = blockIdx.x * blockDim.x + threadIdx.x;
    if (i < total4) {
        float4 v = ((const float4*)x)[i];
        __half2* o = (__half2*)g_x16;
        o[2 * i]     = __floats2half2_rn(v.x, v.y);
        o[2 * i + 1] = __floats2half2_rn(v.z, v.w);
    }
}

// ---------------- fp16 tensor-core GEMM + fused attention dots ---------------
// h = x @ W. Single K=128 smem tile: load once, 8 k-steps of m16n8k16, done.
// A from xs [row][k] fp16; B from ws [n][k] fp16 (pre-transposed in gmem).
__global__ void __launch_bounds__(256, 2) gemm_kernel(
    const float* __restrict__ att_s, const float* __restrict__ att_d, int n)
{
    extern __shared__ char smemc[];
    __half* xs = (__half*)smemc;
    __half* ws = (__half*)(smemc + XS16_BYTES);

    int tid  = threadIdx.x;
    int lane = tid & 31, wid = tid >> 5;
    int g    = lane >> 2, tig = lane & 3;
    int wm   = wid & 3,   wn  = wid >> 2;      // 4(M) x 2(N)
    int row0 = blockIdx.x * BM;

    // ---- load whole tile (cp.async), one shot ----
    #pragma unroll
    for (int t = 0; t < 4; t++) {              // xs: 64 rows x 16 chunks
        int q = tid + t * 256;
        int r = q >> 4, kc = q & 15;
        int grow = row0 + r;
        cp16(xs + r * XS16_STRIDE + kc * 8,
             g_x16 + (size_t)grow * IN_DIM + kc * 8, grow < n);
    }
    #pragma unroll
    for (int t = 0; t < 16; t++) {             // ws: 256 rows x 16 chunks
        int q = tid + t * 256;
        int nr = q >> 4, kc = q & 15;
        cp16(ws + nr * WS16_STRIDE + kc * 8,
             g_wt16 + (size_t)nr * IN_DIM + kc * 8, true);
    }
    asm volatile("cp.async.commit_group;" ::: "memory");
    asm volatile("cp.async.wait_group 0;" ::: "memory");
    __syncthreads();

    float4 acc[16];
    #pragma unroll
    for (int t = 0; t < 16; t++) acc[t] = make_float4(0.f, 0.f, 0.f, 0.f);

    #pragma unroll
    for (int ks = 0; ks < 8; ks++) {
        int kk = ks * 16;
        const __half* xrow0 = xs + (wm * 16 + g) * XS16_STRIDE + kk + 2 * tig;
        const __half* xrow8 = xrow0 + 8 * XS16_STRIDE;
        unsigned a0 = *(const unsigned*)(xrow0);
        unsigned a1 = *(const unsigned*)(xrow8);
        unsigned a2 = *(const unsigned*)(xrow0 + 8);
        unsigned a3 = *(const unsigned*)(xrow8 + 8);
        const __half* wb = ws + (size_t)(wn * 128 + g) * WS16_STRIDE + kk + 2 * tig;
        #pragma unroll
        for (int nc = 0; nc < 4; nc++) {
            unsigned bq[8];
            #pragma unroll
            for (int j = 0; j < 4; j++) {
                const __half* wp = wb + (nc * 4 + j) * 8 * WS16_STRIDE;
                bq[2 * j]     = *(const unsigned*)(wp);
                bq[2 * j + 1] = *(const unsigned*)(wp + 8);
            }
            #pragma unroll
            for (int j = 0; j < 4; j++)
                mma_f16(acc[nc * 4 + j], a0, a1, a2, a3, bq[2 * j], bq[2 * j + 1]);
        }
    }
    __syncthreads();

    // ---- epilogue: D -> smem row-major (R8/R14-verified), then h + dots -----
    float* Dsm = (float*)smemc;                // 64 x 260 x 4 = 66.6KB <= 87KB
    {
        int rbase = wm * 16;
        int cbase = wn * 128 + tig * 2;
        #pragma unroll
        for (int nt = 0; nt < 16; nt++) {
            int c = cbase + nt * 8;
            *(float2*)(Dsm + (rbase + g) * D_STRIDE + c)     = make_float2(acc[nt].x, acc[nt].y);
            *(float2*)(Dsm + (rbase + g + 8) * D_STRIDE + c) = make_float2(acc[nt].z, acc[nt].w);
        }
    }
    __syncthreads();

    {
        int row  = tid >> 2, part = tid & 3;
        int grow = row0 + row;
        if (grow < n) {
            int c0 = part * 64;
            float d[64];
            #pragma unroll
            for (int i = 0; i < 16; i++)
                *(float4*)(d + i * 4) = *(const float4*)(Dsm + row * D_STRIDE + c0 + i * 4);

            __half2 hv[4];
            #pragma unroll
            for (int i = 0; i < 8; i++) {
                #pragma unroll
                for (int p = 0; p < 4; p++)
                    hv[p] = __floats2half2_rn(d[i * 8 + 2 * p], d[i * 8 + 2 * p + 1]);
                *(uint4*)(g_hh + (size_t)grow * HID + c0 + i * 8) = *(uint4*)hv;
            }

            float s0 = 0.f, s1 = 0.f, t0 = 0.f, t1 = 0.f;
            #pragma unroll
            for (int j = 0; j < 32; j++) {
                s0 += d[j]      * att_s[c0 + j];
                t0 += d[j]      * att_d[c0 + j];
                s1 += d[j + 32] * att_s[c0 + 32 + j];
                t1 += d[j + 32] * att_d[c0 + 32 + j];
            }
            int h0 = 2 * part;
            g_asrc[grow * HEADS + h0]     = s0;
            g_asrc[grow * HEADS + h0 + 1] = s1;
            g_adst[grow * HEADS + h0]     = t0;
            g_adst[grow * HEADS + h0 + 1] = t1;
        }
    }
}

// ---------------- degree histogram + per-edge rank ---------------------------
__global__ void deg_kernel(const int* __restrict__ ei, int e, int n) {
    int i = blockIdx.x * blockDim.x + threadIdx.x;
    if (i < e) {
        int d = ei[e + i];   // dst row of edge_index [2, E]
        int r = 0;
        if ((unsigned)d < (unsigned)n) r = atomicAdd(&g_deg[d], 1);
        g_rank[i] = r;
    }
}

// ---------------- 3-kernel exclusive scan ------------------------------------
__device__ __forceinline__ int block_scan_incl(int v, int tid) {
    __shared__ int wsum[8];
    int lane = tid & 31, w = tid >> 5;
    int x = v;
    #pragma unroll
    for (int o = 1; o < 32; o <<= 1) {
        int y = __shfl_up_sync(0xffffffffu, x, o);
        if (lane >= o) x += y;
    }
    if (lane == 31) wsum[w] = x;
    __syncthreads();
    if (tid < 8) {
        int y = wsum[tid];
        #pragma unroll
        for (int o = 1; o < 8; o <<= 1) {
            int z = __shfl_up_sync(0xffu, y, o);
            if (tid >= o) y += z;
        }
        wsum[tid] = y;
    }
    __syncthreads();
    int base = (w > 0) ? wsum[w - 1] : 0;
    return x + base;
}

__global__ void scan_a_kernel(int n) {
    int i = blockIdx.x * 256 + threadIdx.x;
    int v = (i < n) ? g_deg[i] : 0;
    int incl = block_scan_incl(v, threadIdx.x);
    if (i < n) g_off[i] = incl - v;
    if (threadIdx.x == 255) g_bsum[blockIdx.x] = incl;
}

__global__ void scan_b_kernel(int nb) {
    int t = threadIdx.x;
    int v = (t < nb) ? g_bsum[t] : 0;
    int incl = block_scan_incl(v, t);
    g_bbase[t] = incl - v;
}

__global__ void scan_c_kernel(int n, int e) {
    int i = blockIdx.x * 256 + threadIdx.x;
    if (i < n) g_off[i] += g_bbase[blockIdx.x];
    if (i == 0) g_off[n] = e;
}

// ---------------- CSR fill (atomic-free: uses deg-phase ranks) ---------------
__global__ void fill_kernel(const int* __restrict__ ei, int e, int n) {
    int i = blockIdx.x * blockDim.x + threadIdx.x;
    if (i < e) {
        int d = ei[e + i];
        int s = ei[i];
        if ((unsigned)d < (unsigned)n)
            g_csrc[g_off[d] + g_rank[i]] = s;
    }
}

// ---------------- single-pass softmax + aggregate (R14-proven version) -------
__global__ __launch_bounds__(256) void agg_kernel(
    const float* __restrict__ bias, float* __restrict__ out, int n)
{
    int warp = (blockIdx.x * blockDim.x + threadIdx.x) >> 5;
    int lane = threadIdx.x & 31;
    if (warp >= n) return;
    int node = warp;
    int beg = g_off[node];
    int cnt = g_off[node + 1] - beg + 1;     // edges + self loop

    int eslot = lane >> 3, head8 = lane & 7; // logit role
    int hsel  = lane >> 2;                   // accumulation head

    float adl = g_adst[node * HEADS + head8];

    float acc[8];
    #pragma unroll
    for (int j = 0; j < 8; j++) acc[j] = 0.f;
    float s_part = 0.f;                      // partial denom for head8

    for (int base = 0; base < cnt; base += 4) {
        int pos = base + eslot;
        bool valid = pos < cnt;
        int src_e = (pos < cnt - 1) ? g_csrc[beg + pos] : node;
        float a = g_asrc[src_e * HEADS + head8];
        float ev = a + adl;
        ev = ev > 0.f ? ev : NEG * ev;
        float ex = valid ? __expf(ev) : 0.f;
        s_part += ex;

        int   sj[4];
        float exj[4];
        #pragma unroll
        for (int j = 0; j < 4; j++) {
            sj[j]  = __shfl_sync(0xffffffffu, src_e, j * 8);
            exj[j] = __shfl_sync(0xffffffffu, ex, j * 8 + hsel);
        }
        uint4 hr[4];
        #pragma unroll
        for (int j = 0; j < 4; j++)
            hr[j] = *(const uint4*)(g_hh + (size_t)sj[j] * HID + lane * 8);
        #pragma unroll
        for (int j = 0; j < 4; j++) {
            const __half2* hh = (const __half2*)&hr[j];
            #pragma unroll
            for (int k2 = 0; k2 < 4; k2++) {
                float2 f = __half22float2(hh[k2]);
                acc[2 * k2]     = fmaf(exj[j], f.x, acc[2 * k2]);
                acc[2 * k2 + 1] = fmaf(exj[j], f.y, acc[2 * k2 + 1]);
            }
        }
    }

    // fold the 4 edge-slot groups' denominators (lanes with same head8)
    s_part += __shfl_xor_sync(0xffffffffu, s_part, 8);
    s_part += __shfl_xor_sync(0xffffffffu, s_part, 16);
    float inv_l = __frcp_rn(s_part);         // every lane: inv for head8
    float invk = __shfl_sync(0xffffffffu, inv_l, hsel) * 0.125f;
    #pragma unroll
    for (int j = 0; j < 8; j++) acc[j] *= invk;
    #pragma unroll
    for (int o = 4; o < 32; o <<= 1)
        #pragma unroll
        for (int j = 0; j < 8; j++)
            acc[j] += __shfl_xor_sync(0xffffffffu, acc[j], o);

    if (lane < 4) {
        int c0 = lane * 8;
        float4 o0 = make_float4(acc[0] + bias[c0],     acc[1] + bias[c0 + 1],
                                acc[2] + bias[c0 + 2], acc[3] + bias[c0 + 3]);
        float4 o1 = make_float4(acc[4] + bias[c0 + 4], acc[5] + bias[c0 + 5],
                                acc[6] + bias[c0 + 6], acc[7] + bias[c0 + 7]);
        *(float4*)(out + node * ODIM + c0)     = o0;
        *(float4*)(out + node * ODIM + c0 + 4) = o1;
    }
}

// ---------------- launcher: fork/join stream overlap -------------------------
extern "C" void kernel_launch(void* const* d_in, const int* in_sizes, int n_in,
                              void* d_out, int out_size)
{
    const float* x     = (const float*)d_in[0];
    const int*   ei    = (const int*)d_in[1];   // [2, E] — int32 (JAX x64 off)
    const float* W     = (const float*)d_in[3];
    const float* att_s = (const float*)d_in[4];
    const float* att_d = (const float*)d_in[5];
    const float* bias  = (const float*)d_in[6];
    float*       out   = (float*)d_out;

    int n = in_sizes[0] / IN_DIM;
    int e = in_sizes[1] / 2;
    int nb = (n + 255) / 256;
    int total4 = n * IN_DIM / 4;

    cudaFuncSetAttribute(gemm_kernel,
                         cudaFuncAttributeMaxDynamicSharedMemorySize, GSMEM_BYTES);

    cudaStream_t s1;
    cudaEvent_t ev_fork, ev_join;
    cudaStreamCreateWithFlags(&s1, cudaStreamNonBlocking);
    cudaEventCreateWithFlags(&ev_fork, cudaEventDisableTiming);
    cudaEventCreateWithFlags(&ev_join, cudaEventDisableTiming);

    // main stream: zero (g_deg + W cvt) first — both branches depend on it
    zero_kernel<<<nb, 256, 0, 0>>>(W, n);
    cudaEventRecord(ev_fork, 0);

    // side stream: CSR build chain
    cudaStreamWaitEvent(s1, ev_fork, 0);
    deg_kernel<<<(e + 255) / 256, 256, 0, s1>>>(ei, e, n);
    scan_a_kernel<<<nb, 256, 0, s1>>>(n);
    scan_b_kernel<<<1, 256, 0, s1>>>(nb);
    scan_c_kernel<<<nb, 256, 0, s1>>>(n, e);
    fill_kernel<<<(e + 255) / 256, 256, 0, s1>>>(ei, e, n);
    cudaEventRecord(ev_join, s1);

    // main stream: x->fp16 then GEMM, concurrent with CSR build
    xcvt_kernel<<<(total4 + 255) / 256, 256, 0, 0>>>(x, total4);
    gemm_kernel<<<(n + BM - 1) / BM, 256, GSMEM_BYTES, 0>>>(att_s, att_d, n);

    // join, then aggregate
    cudaStreamWaitEvent(0, ev_join, 0);
    agg_kernel<<<(n * 32 + 255) / 256, 256, 0, 0>>>(bias, out, n);
}